// round 1
// baseline (speedup 1.0000x reference)
#include <cuda_runtime.h>
#include <cstdint>
#include <math.h>

#define ORDER   8
#define IN_SZ   512
#define OUT_SZ  512
#define BATCH   4096
#define KK      (ORDER * IN_SZ)   // 4096 inner dim (k = 1..8 folded; k=0 -> bias)
#define NT      (KK / 16)         // 256 GEMM k-tiles

// Scratch (static __device__ arrays; no allocation)
__device__ float g_J[(size_t)BATCH * KK];    // [b][(k-1)*IN + i]
__device__ float g_W2[(size_t)OUT_SZ * KK];  // [o][(k-1)*IN + i]
__device__ float g_bias[OUT_SZ];

// ---------------------------------------------------------------------------
// packed f32x2 helpers (SASS FFMA2 path — only reachable via PTX)
// ---------------------------------------------------------------------------
#define FMA_F32X2(d, a, b, c) \
    asm("fma.rn.f32x2 %0, %1, %2, %3;" : "=l"(d) : "l"(a), "l"(b), "l"(c))

#define BCAST_F32X2(u, f) \
    asm("mov.b64 %0, {%1, %2};" : "=l"(u) : "f"(f), "f"(f))

#define UNPACK_F32X2_(lo, hi, in) \
    asm("mov.b64 {%0, %1}, %2;" : "=f"(lo), "=f"(hi) : "l"(in))

// ---------------------------------------------------------------------------
// Kernel 1: fold weights into coefficients. W2[o][cc] = coeff[o][i][k]*w[o][i]
//           bias[o] = sum_i coeff[o][i][0]*w[o][i]   (J_0 == 1)
// ---------------------------------------------------------------------------
__global__ void wprep_kernel(const float* __restrict__ w,
                             const float* __restrict__ coeff) {
    const int o = blockIdx.x;
    __shared__ float red[256];
    float acc = 0.f;
    for (int i = threadIdx.x; i < IN_SZ; i += 256) {
        const float wv = w[o * IN_SZ + i];
        const float* c = coeff + ((size_t)o * IN_SZ + i) * (ORDER + 1);
        acc += c[0] * wv;
#pragma unroll
        for (int k = 1; k <= ORDER; k++)
            g_W2[(size_t)o * KK + (k - 1) * IN_SZ + i] = c[k] * wv;
    }
    red[threadIdx.x] = acc;
    __syncthreads();
    for (int s = 128; s > 0; s >>= 1) {
        if (threadIdx.x < s) red[threadIdx.x] += red[threadIdx.x + s];
        __syncthreads();
    }
    if (threadIdx.x == 0) g_bias[o] = red[0];
}

// ---------------------------------------------------------------------------
// Kernel 2: Jacobi values J_k(tanh(x)) for k=1..ORDER (alpha=beta=1)
// ---------------------------------------------------------------------------
__global__ void jgen_kernel(const float* __restrict__ x) {
    const int idx = blockIdx.x * blockDim.x + threadIdx.x;
    if (idx >= BATCH * IN_SZ) return;
    const int b = idx >> 9;       // / IN_SZ
    const int i = idx & (IN_SZ - 1);

    const float t = tanhf(x[idx]);
    float pm1 = 1.0f;
    float p   = 2.0f * t;          // 0.5*(a+b+2)*t - 0.5*(a-b), a=b=1
    float* Jrow = g_J + (size_t)b * KK + i;
    Jrow[0] = p;                   // k = 1
#pragma unroll
    for (int n = 2; n <= ORDER; n++) {
        const double a = 1.0, bb = 1.0;
        const float k1 = (float)((2.0 * n + a + bb) * (2.0 * n + a + bb - 1.0) /
                                 (2.0 * n * (n + a + bb)));
        const float k2 = (float)((2.0 * n + a + bb - 1.0) * (a * a - bb * bb) /
                                 (2.0 * n * (n + a + bb) * (2.0 * n + a + bb - 2.0)));
        const float k3 = (float)((n + a - 1.0) * (n + bb - 1.0) * (2.0 * n + a + bb) /
                                 (n * (n + a + bb) * (2.0 * n + a + bb - 2.0)));
        const float pn = (k1 * t + k2) * p - k3 * pm1;
        pm1 = p;
        p   = pn;
        Jrow[(n - 1) * IN_SZ] = p;
    }
}

// ---------------------------------------------------------------------------
// Kernel 3: C[b][o] = bias[o] + sum_cc J[b][cc] * W2[o][cc]
// 128x128 block tile, BK=16, 256 threads, 8x8 microtile via packed f32x2 FMA,
// register-prefetch software pipeline.
// ---------------------------------------------------------------------------
#define BM 128
#define BN 128
#define BK 16

__global__ void __launch_bounds__(256, 1)
gemm_kernel(float* __restrict__ C) {
    __shared__ __align__(16) float As[BK][BM];
    __shared__ __align__(16) float Bs[BK][BN];

    const int tid = threadIdx.x;
    const int tx  = tid & 15;   // along N (o)
    const int ty  = tid >> 4;   // along M (b)
    const int bm  = blockIdx.y * BM;
    const int bn  = blockIdx.x * BN;

    const float* A = g_J  + (size_t)bm * KK;
    const float* B = g_W2 + (size_t)bn * KK;

    // global->shared load mapping: 512 float4 per tile per matrix, 2 per thread
    const int r0 = tid >> 2;          // row for load 0
    const int c0 = (tid & 3) * 4;     // col for load 0
    const int r1 = (tid + 256) >> 2;  // row for load 1
    const int c1 = c0;

    unsigned long long acc[4][8];
#pragma unroll
    for (int mp = 0; mp < 4; mp++)
#pragma unroll
        for (int j = 0; j < 8; j++) acc[mp][j] = 0ULL;

    // prologue: fill smem for tile 0
    {
        float4 va0 = *(const float4*)(A + (size_t)r0 * KK + c0);
        float4 va1 = *(const float4*)(A + (size_t)r1 * KK + c1);
        float4 vb0 = *(const float4*)(B + (size_t)r0 * KK + c0);
        float4 vb1 = *(const float4*)(B + (size_t)r1 * KK + c1);
        As[c0 + 0][r0] = va0.x; As[c0 + 1][r0] = va0.y; As[c0 + 2][r0] = va0.z; As[c0 + 3][r0] = va0.w;
        As[c1 + 0][r1] = va1.x; As[c1 + 1][r1] = va1.y; As[c1 + 2][r1] = va1.z; As[c1 + 3][r1] = va1.w;
        Bs[c0 + 0][r0] = vb0.x; Bs[c0 + 1][r0] = vb0.y; Bs[c0 + 2][r0] = vb0.z; Bs[c0 + 3][r0] = vb0.w;
        Bs[c1 + 0][r1] = vb1.x; Bs[c1 + 1][r1] = vb1.y; Bs[c1 + 2][r1] = vb1.z; Bs[c1 + 3][r1] = vb1.w;
    }
    __syncthreads();

#pragma unroll 1
    for (int kt = 0; kt < NT; kt++) {
        // prefetch next tile into registers (LDG in flight during compute)
        float4 pa0, pa1, pb0, pb1;
        if (kt + 1 < NT) {
            const int kb = (kt + 1) * BK;
            pa0 = *(const float4*)(A + (size_t)r0 * KK + kb + c0);
            pa1 = *(const float4*)(A + (size_t)r1 * KK + kb + c1);
            pb0 = *(const float4*)(B + (size_t)r0 * KK + kb + c0);
            pb1 = *(const float4*)(B + (size_t)r1 * KK + kb + c1);
        }

#pragma unroll
        for (int k = 0; k < BK; k++) {
            const ulonglong2 aA = *(const ulonglong2*)&As[k][ty * 8];
            const ulonglong2 aB = *(const ulonglong2*)&As[k][ty * 8 + 4];
            const unsigned long long au[4] = {aA.x, aA.y, aB.x, aB.y};
            const float4 b0 = *(const float4*)&Bs[k][tx * 8];
            const float4 b1 = *(const float4*)&Bs[k][tx * 8 + 4];
            unsigned long long bu[8];
            BCAST_F32X2(bu[0], b0.x); BCAST_F32X2(bu[1], b0.y);
            BCAST_F32X2(bu[2], b0.z); BCAST_F32X2(bu[3], b0.w);
            BCAST_F32X2(bu[4], b1.x); BCAST_F32X2(bu[5], b1.y);
            BCAST_F32X2(bu[6], b1.z); BCAST_F32X2(bu[7], b1.w);
#pragma unroll
            for (int mp = 0; mp < 4; mp++)
#pragma unroll
                for (int j = 0; j < 8; j++)
                    FMA_F32X2(acc[mp][j], au[mp], bu[j], acc[mp][j]);
        }
        __syncthreads();

        if (kt + 1 < NT) {
            As[c0 + 0][r0] = pa0.x; As[c0 + 1][r0] = pa0.y; As[c0 + 2][r0] = pa0.z; As[c0 + 3][r0] = pa0.w;
            As[c1 + 0][r1] = pa1.x; As[c1 + 1][r1] = pa1.y; As[c1 + 2][r1] = pa1.z; As[c1 + 3][r1] = pa1.w;
            Bs[c0 + 0][r0] = pb0.x; Bs[c0 + 1][r0] = pb0.y; Bs[c0 + 2][r0] = pb0.z; Bs[c0 + 3][r0] = pb0.w;
            Bs[c1 + 0][r1] = pb1.x; Bs[c1 + 1][r1] = pb1.y; Bs[c1 + 2][r1] = pb1.z; Bs[c1 + 3][r1] = pb1.w;
            __syncthreads();
        }
    }

    // epilogue: unpack pairs (rows 2mp, 2mp+1), add bias, vector store
    float bias_v[8];
#pragma unroll
    for (int j = 0; j < 8; j++) bias_v[j] = g_bias[bn + tx * 8 + j];

#pragma unroll
    for (int mp = 0; mp < 4; mp++) {
        float r0v[8], r1v[8];
#pragma unroll
        for (int j = 0; j < 8; j++) {
            float lo, hi;
            UNPACK_F32X2_(lo, hi, acc[mp][j]);
            r0v[j] = lo + bias_v[j];
            r1v[j] = hi + bias_v[j];
        }
        const int gm0 = bm + ty * 8 + mp * 2;
        float* out0 = C + (size_t)gm0 * OUT_SZ + bn + tx * 8;
        float* out1 = out0 + OUT_SZ;
        *(float4*)(out0)     = make_float4(r0v[0], r0v[1], r0v[2], r0v[3]);
        *(float4*)(out0 + 4) = make_float4(r0v[4], r0v[5], r0v[6], r0v[7]);
        *(float4*)(out1)     = make_float4(r1v[0], r1v[1], r1v[2], r1v[3]);
        *(float4*)(out1 + 4) = make_float4(r1v[4], r1v[5], r1v[6], r1v[7]);
    }
}

// ---------------------------------------------------------------------------
extern "C" void kernel_launch(void* const* d_in, const int* in_sizes, int n_in,
                              void* d_out, int out_size) {
    const float* x       = (const float*)d_in[0];  // [4096, 512]
    const float* weights = (const float*)d_in[1];  // [512, 512]
    const float* coeff   = (const float*)d_in[2];  // [512, 512, 9]
    float* out = (float*)d_out;                    // [4096, 512]

    wprep_kernel<<<OUT_SZ, 256>>>(weights, coeff);
    jgen_kernel<<<(BATCH * IN_SZ) / 256, 256>>>(x);
    dim3 grid(OUT_SZ / BN, BATCH / BM);
    gemm_kernel<<<grid, 256>>>(out);
}

// round 10
// speedup vs baseline: 3.1135x; 3.1135x over previous
#include <cuda_runtime.h>
#include <cuda_bf16.h>
#include <cstdint>
#include <math.h>

#define ORDER   8
#define IN_SZ   512
#define OUT_SZ  512
#define BATCH   4096
#define KK      4096              // inner dim (k=1..8 folded; k=0 -> bias)
#define BM      128
#define BN      128
#define BK      64
#define NTILE   (KK / BK)         // 64 k-chunks
#define STAGES  3

// split-bf16 operands (h + l reconstructs fp32 to ~2^-17)
__device__ __align__(256) __nv_bfloat16 g_Jh[(size_t)BATCH * KK];
__device__ __align__(256) __nv_bfloat16 g_Jl[(size_t)BATCH * KK];
__device__ __align__(256) __nv_bfloat16 g_Wh[(size_t)OUT_SZ * KK];
__device__ __align__(256) __nv_bfloat16 g_Wl[(size_t)OUT_SZ * KK];
__device__ float g_bias[OUT_SZ];

// ---------------------------------------------------------------------------
// helpers (baseline PTX only: cp.async / ldmatrix / mma.sync — no tcgen05)
// ---------------------------------------------------------------------------
__device__ __forceinline__ uint32_t s2u(const void* p) {
    uint32_t a;
    asm("{ .reg .u64 t; cvta.to.shared.u64 t, %1; cvt.u32.u64 %0, t; }"
        : "=r"(a) : "l"(p));
    return a;
}

#define SWZ(x) ((x) ^ (((x) >> 3) & 0x70))   // 128B-row xor swizzle

#define CP16(dst, src) \
    asm volatile("cp.async.cg.shared.global [%0], [%1], 16;" \
                 :: "r"(dst), "l"(__cvta_generic_to_global(src)) : "memory")

#define LDSM4(r0, r1, r2, r3, addr) \
    asm volatile("ldmatrix.sync.aligned.m8n8.x4.shared.b16 {%0,%1,%2,%3}, [%4];" \
                 : "=r"(r0), "=r"(r1), "=r"(r2), "=r"(r3) : "r"(addr))

#define MMA(c, a, b0, b1) \
    asm volatile("mma.sync.aligned.m16n8k16.row.col.f32.bf16.bf16.f32 " \
                 "{%0,%1,%2,%3},{%4,%5,%6,%7},{%8,%9},{%0,%1,%2,%3};" \
                 : "+f"((c)[0]), "+f"((c)[1]), "+f"((c)[2]), "+f"((c)[3]) \
                 : "r"((a)[0]), "r"((a)[1]), "r"((a)[2]), "r"((a)[3]), \
                   "r"(b0), "r"(b1))

// ---------------------------------------------------------------------------
// Kernel 1: W2[o][cc] = coeff[o][i][k]*w[o][i] split to bf16 h/l; bias from k=0
// ---------------------------------------------------------------------------
__global__ void wprep_kernel(const float* __restrict__ w,
                             const float* __restrict__ coeff) {
    const int o = blockIdx.x;
    __shared__ float red[256];
    float acc = 0.f;
    for (int i = threadIdx.x; i < IN_SZ; i += 256) {
        const float wv = w[o * IN_SZ + i];
        const float* c = coeff + ((size_t)o * IN_SZ + i) * (ORDER + 1);
        acc += c[0] * wv;
#pragma unroll
        for (int k = 1; k <= ORDER; k++) {
            const float v = c[k] * wv;
            const __nv_bfloat16 h = __float2bfloat16(v);
            const __nv_bfloat16 l = __float2bfloat16(v - __bfloat162float(h));
            const size_t off = (size_t)o * KK + (size_t)(k - 1) * IN_SZ + i;
            g_Wh[off] = h;
            g_Wl[off] = l;
        }
    }
    red[threadIdx.x] = acc;
    __syncthreads();
    for (int s = 128; s > 0; s >>= 1) {
        if (threadIdx.x < s) red[threadIdx.x] += red[threadIdx.x + s];
        __syncthreads();
    }
    if (threadIdx.x == 0) g_bias[o] = red[0];
}

// ---------------------------------------------------------------------------
// Kernel 2: Jacobi values (alpha=beta=1), split to bf16 h/l, 2 elems/thread
// ---------------------------------------------------------------------------
__global__ void jgen_kernel(const float* __restrict__ x) {
    const int g = blockIdx.x * blockDim.x + threadIdx.x;
    const int e = g * 2;
    const int b = e >> 9;
    const int i = e & (IN_SZ - 1);
    const float2 xv = *(const float2*)(x + e);
    const float t0 = tanhf(xv.x);
    const float t1 = tanhf(xv.y);

    const size_t base = (size_t)b * KK + i;

    float pm0 = 1.0f, pm1 = 1.0f;
    float p0 = 2.0f * t0, p1 = 2.0f * t1;

    auto stp = [&](int n, float a0, float a1) {
        const __nv_bfloat16 h0 = __float2bfloat16(a0);
        const __nv_bfloat16 h1 = __float2bfloat16(a1);
        const __nv_bfloat16 l0 = __float2bfloat16(a0 - __bfloat162float(h0));
        const __nv_bfloat16 l1 = __float2bfloat16(a1 - __bfloat162float(h1));
        const size_t off = base + (size_t)(n - 1) * IN_SZ;
        *(__nv_bfloat162*)(g_Jh + off) = __halves2bfloat162(h0, h1);
        *(__nv_bfloat162*)(g_Jl + off) = __halves2bfloat162(l0, l1);
    };

    stp(1, p0, p1);
#pragma unroll
    for (int n = 2; n <= ORDER; n++) {
        const double a = 1.0, bb = 1.0;
        const float k1 = (float)((2.0 * n + a + bb) * (2.0 * n + a + bb - 1.0) /
                                 (2.0 * n * (n + a + bb)));
        const float k2 = (float)((2.0 * n + a + bb - 1.0) * (a * a - bb * bb) /
                                 (2.0 * n * (n + a + bb) * (2.0 * n + a + bb - 2.0)));
        const float k3 = (float)((n + a - 1.0) * (n + bb - 1.0) * (2.0 * n + a + bb) /
                                 (n * (n + a + bb) * (2.0 * n + a + bb - 2.0)));
        const float pn0 = (k1 * t0 + k2) * p0 - k3 * pm0;
        const float pn1 = (k1 * t1 + k2) * p1 - k3 * pm1;
        pm0 = p0; pm1 = p1;
        p0 = pn0; p1 = pn1;
        stp(n, p0, p1);
    }
}

// ---------------------------------------------------------------------------
// Kernel 3: HMMA GEMM. C[b][o] = bias[o] + (Jh+Jl)[b]·(Wh+Wl)[o] (3 products)
// 128x128x64 CTA tile, 3-stage cp.async, 8 warps (4x2 grid of 32x64 tiles),
// mma.sync m16n8k16 bf16 -> fp32 register accumulators.
// smem: stage s at base + s*65536: {Ah, Al, Bh, Bl} x 16KB (128 rows x 128B, SWZ)
// ---------------------------------------------------------------------------
#define SLOT_BYTES 65536
#define SMEM_TOTAL (STAGES * SLOT_BYTES + 1024)

__global__ void __launch_bounds__(256, 1) gemm_hmma(float* __restrict__ C) {
    extern __shared__ __align__(1024) char smem_raw[];
    const uint32_t sbr = s2u(smem_raw);
    const uint32_t ab = (sbr + 1023u) & ~1023u;   // 1024-aligned smem base

    const int tid  = threadIdx.x;
    const int wid  = tid >> 5;
    const int lane = tid & 31;
    const int bm = blockIdx.y * BM;
    const int bn = blockIdx.x * BN;

    const int wm = (wid >> 1) * 32;   // warp M offset (4 warps along M)
    const int wn = (wid & 1) * 64;    // warp N offset (2 warps along N)

    // ---- cp.async mapping: 4 tiles x 1024 16B-chunks / 256 threads = 16/thread
    uint32_t dsw[4];
    size_t aoff[4], boff[4];
#pragma unroll
    for (int j = 0; j < 4; j++) {
        const int c = tid + 256 * j;
        const int row = c >> 3;
        const int col = c & 7;
        dsw[j] = SWZ((uint32_t)(row * 128 + col * 16));
        aoff[j] = (size_t)(bm + row) * KK + col * 8;
        boff[j] = (size_t)(bn + row) * KK + col * 8;
    }

    auto load_tile = [&](int kt, int s) {
        const uint32_t base = ab + (uint32_t)s * SLOT_BYTES;
        const size_t ko = (size_t)kt * BK;
#pragma unroll
        for (int j = 0; j < 4; j++) {
            CP16(base +          dsw[j], g_Jh + aoff[j] + ko);
            CP16(base + 16384u + dsw[j], g_Jl + aoff[j] + ko);
            CP16(base + 32768u + dsw[j], g_Wh + boff[j] + ko);
            CP16(base + 49152u + dsw[j], g_Wl + boff[j] + ko);
        }
        asm volatile("cp.async.commit_group;" ::: "memory");
    };

    // ---- ldmatrix per-lane address pre-terms
    // A (x4): lanes 0-15 -> rows m0..m0+15 at k-chunk lo; 16-31 -> same rows, hi
    uint32_t aTerm[2], aRk[2];
    const uint32_t ahi = (uint32_t)(lane >> 4);
#pragma unroll
    for (int mb = 0; mb < 2; mb++) {
        const uint32_t ra = (uint32_t)(wm + mb * 16 + (lane & 15));
        aTerm[mb] = ra * 128u;
        aRk[mb]   = ra & 7u;
    }
    // B (x4): lanes 0-7 n0..7 lo, 8-15 n0..7 hi, 16-23 n8..15 lo, 24-31 n8..15 hi
    uint32_t bTerm[4], bRk[4];
    const uint32_t bhi = (uint32_t)((lane >> 3) & 1);
#pragma unroll
    for (int p = 0; p < 4; p++) {
        const uint32_t rb = (uint32_t)(wn + p * 16 + ((lane >> 4) << 3) + (lane & 7));
        bTerm[p] = rb * 128u;
        bRk[p]   = rb & 7u;
    }

    float acc[2][8][4];
#pragma unroll
    for (int mb = 0; mb < 2; mb++)
#pragma unroll
        for (int nb = 0; nb < 8; nb++)
#pragma unroll
            for (int q = 0; q < 4; q++) acc[mb][nb][q] = 0.f;

    // prologue: stages 0,1
    load_tile(0, 0);
    load_tile(1, 1);

#pragma unroll 1
    for (int kt = 0; kt < NTILE; kt++) {
        if (kt < NTILE - 1) asm volatile("cp.async.wait_group 1;" ::: "memory");
        else                asm volatile("cp.async.wait_group 0;" ::: "memory");
        __syncthreads();

        if (kt + 2 < NTILE) load_tile(kt + 2, (kt + 2) % STAGES);

        const uint32_t sb = ab + (uint32_t)(kt % STAGES) * SLOT_BYTES;

#pragma unroll
        for (int ks = 0; ks < 4; ks++) {
            const uint32_t kcA = 2u * ks + ahi;
            const uint32_t kcB = 2u * ks + bhi;

            uint32_t ah[2][4], al[2][4];
#pragma unroll
            for (int mb = 0; mb < 2; mb++) {
                const uint32_t off = aTerm[mb] + ((kcA ^ aRk[mb]) << 4);
                LDSM4(ah[mb][0], ah[mb][1], ah[mb][2], ah[mb][3], sb + off);
                LDSM4(al[mb][0], al[mb][1], al[mb][2], al[mb][3], sb + 16384u + off);
            }

#pragma unroll
            for (int p = 0; p < 4; p++) {
                const uint32_t off = bTerm[p] + ((kcB ^ bRk[p]) << 4);
                uint32_t bh[4], bl[4];
                LDSM4(bh[0], bh[1], bh[2], bh[3], sb + 32768u + off);
                LDSM4(bl[0], bl[1], bl[2], bl[3], sb + 49152u + off);
                const int n0 = 2 * p, n1 = 2 * p + 1;
                // hh
                MMA(acc[0][n0], ah[0], bh[0], bh[1]);
                MMA(acc[0][n1], ah[0], bh[2], bh[3]);
                MMA(acc[1][n0], ah[1], bh[0], bh[1]);
                MMA(acc[1][n1], ah[1], bh[2], bh[3]);
                // lh
                MMA(acc[0][n0], al[0], bh[0], bh[1]);
                MMA(acc[0][n1], al[0], bh[2], bh[3]);
                MMA(acc[1][n0], al[1], bh[0], bh[1]);
                MMA(acc[1][n1], al[1], bh[2], bh[3]);
                // hl
                MMA(acc[0][n0], ah[0], bl[0], bl[1]);
                MMA(acc[0][n1], ah[0], bl[2], bl[3]);
                MMA(acc[1][n0], ah[1], bl[0], bl[1]);
                MMA(acc[1][n1], ah[1], bl[2], bl[3]);
            }
        }
    }

    // epilogue: fragment -> global, + bias
#pragma unroll
    for (int mb = 0; mb < 2; mb++) {
        const int row0 = bm + wm + mb * 16 + (lane >> 2);
#pragma unroll
        for (int nb = 0; nb < 8; nb++) {
            const int cn = bn + wn + nb * 8 + (lane & 3) * 2;
            const float b0 = g_bias[cn];
            const float b1 = g_bias[cn + 1];
            float2 v0 = make_float2(acc[mb][nb][0] + b0, acc[mb][nb][1] + b1);
            float2 v1 = make_float2(acc[mb][nb][2] + b0, acc[mb][nb][3] + b1);
            *(float2*)(C + (size_t)row0 * OUT_SZ + cn)       = v0;
            *(float2*)(C + (size_t)(row0 + 8) * OUT_SZ + cn) = v1;
        }
    }
}

// ---------------------------------------------------------------------------
extern "C" void kernel_launch(void* const* d_in, const int* in_sizes, int n_in,
                              void* d_out, int out_size) {
    const float* x       = (const float*)d_in[0];  // [4096, 512]
    const float* weights = (const float*)d_in[1];  // [512, 512]
    const float* coeff   = (const float*)d_in[2];  // [512, 512, 9]
    float* out = (float*)d_out;                    // [4096, 512]

    cudaFuncSetAttribute(gemm_hmma, cudaFuncAttributeMaxDynamicSharedMemorySize,
                         SMEM_TOTAL);

    wprep_kernel<<<OUT_SZ, 256>>>(weights, coeff);
    jgen_kernel<<<(BATCH * IN_SZ / 2) / 256, 256>>>(x);
    dim3 grid(OUT_SZ / BN, BATCH / BM);
    gemm_hmma<<<grid, 256, SMEM_TOTAL>>>(out);
}

// round 12
// speedup vs baseline: 4.3676x; 1.4028x over previous
#include <cuda_runtime.h>
#include <cuda_fp16.h>
#include <cstdint>
#include <math.h>

#define ORDER   8
#define IN_SZ   512
#define OUT_SZ  512
#define BATCH   4096
#define KK      4096              // inner dim (k=1..8 folded; k=0 -> bias)
#define BM      128
#define BN      128
#define BK      64
#define NTILE   (KK / BK)         // 64 k-chunks
#define STAGES  3

// J single fp16 (error source, 2^-12); W split fp16 h+l (exact to ~2^-24)
__device__ __align__(256) __half g_J [(size_t)BATCH  * KK];
__device__ __align__(256) __half g_Wh[(size_t)OUT_SZ * KK];
__device__ __align__(256) __half g_Wl[(size_t)OUT_SZ * KK];
__device__ float g_bias[OUT_SZ];

// ---------------------------------------------------------------------------
// helpers (baseline PTX only: cp.async / ldmatrix / mma.sync — no tcgen05)
// ---------------------------------------------------------------------------
__device__ __forceinline__ uint32_t s2u(const void* p) {
    uint32_t a;
    asm("{ .reg .u64 t; cvta.to.shared.u64 t, %1; cvt.u32.u64 %0, t; }"
        : "=r"(a) : "l"(p));
    return a;
}

#define SWZ(x) ((x) ^ (((x) >> 3) & 0x70))   // 128B-row xor swizzle

#define CP16(dst, src) \
    asm volatile("cp.async.cg.shared.global [%0], [%1], 16;" \
                 :: "r"(dst), "l"(__cvta_generic_to_global(src)) : "memory")

#define LDSM4(r0, r1, r2, r3, addr) \
    asm volatile("ldmatrix.sync.aligned.m8n8.x4.shared.b16 {%0,%1,%2,%3}, [%4];" \
                 : "=r"(r0), "=r"(r1), "=r"(r2), "=r"(r3) : "r"(addr))

#define MMA(c, a, b0, b1) \
    asm volatile("mma.sync.aligned.m16n8k16.row.col.f32.f16.f16.f32 " \
                 "{%0,%1,%2,%3},{%4,%5,%6,%7},{%8,%9},{%0,%1,%2,%3};" \
                 : "+f"((c)[0]), "+f"((c)[1]), "+f"((c)[2]), "+f"((c)[3]) \
                 : "r"((a)[0]), "r"((a)[1]), "r"((a)[2]), "r"((a)[3]), \
                   "r"(b0), "r"(b1))

// ---------------------------------------------------------------------------
// Kernel 1: W2[o][cc] = coeff[o][i][k]*w[o][i] split to fp16 h/l; bias from k=0
// ---------------------------------------------------------------------------
__global__ void wprep_kernel(const float* __restrict__ w,
                             const float* __restrict__ coeff) {
    const int o = blockIdx.x;
    __shared__ float red[256];
    float acc = 0.f;
    for (int i = threadIdx.x; i < IN_SZ; i += 256) {
        const float wv = w[o * IN_SZ + i];
        const float* c = coeff + ((size_t)o * IN_SZ + i) * (ORDER + 1);
        acc += c[0] * wv;
#pragma unroll
        for (int k = 1; k <= ORDER; k++) {
            const float v = c[k] * wv;
            const __half h = __float2half_rn(v);
            const __half l = __float2half_rn(v - __half2float(h));
            const size_t off = (size_t)o * KK + (size_t)(k - 1) * IN_SZ + i;
            g_Wh[off] = h;
            g_Wl[off] = l;
        }
    }
    red[threadIdx.x] = acc;
    __syncthreads();
    for (int s = 128; s > 0; s >>= 1) {
        if (threadIdx.x < s) red[threadIdx.x] += red[threadIdx.x + s];
        __syncthreads();
    }
    if (threadIdx.x == 0) g_bias[o] = red[0];
}

// ---------------------------------------------------------------------------
// Kernel 2: Jacobi values (alpha=beta=1) -> single fp16, 2 elems/thread
// ---------------------------------------------------------------------------
__global__ void jgen_kernel(const float* __restrict__ x) {
    const int g = blockIdx.x * blockDim.x + threadIdx.x;
    const int e = g * 2;
    const int b = e >> 9;
    const int i = e & (IN_SZ - 1);
    const float2 xv = *(const float2*)(x + e);
    const float t0 = tanhf(xv.x);
    const float t1 = tanhf(xv.y);

    const size_t base = (size_t)b * KK + i;

    float pm0 = 1.0f, pm1 = 1.0f;
    float p0 = 2.0f * t0, p1 = 2.0f * t1;

    auto stp = [&](int n, float a0, float a1) {
        const size_t off = base + (size_t)(n - 1) * IN_SZ;
        *(__half2*)(g_J + off) =
            __halves2half2(__float2half_rn(a0), __float2half_rn(a1));
    };

    stp(1, p0, p1);
#pragma unroll
    for (int n = 2; n <= ORDER; n++) {
        const double a = 1.0, bb = 1.0;
        const float k1 = (float)((2.0 * n + a + bb) * (2.0 * n + a + bb - 1.0) /
                                 (2.0 * n * (n + a + bb)));
        const float k2 = (float)((2.0 * n + a + bb - 1.0) * (a * a - bb * bb) /
                                 (2.0 * n * (n + a + bb) * (2.0 * n + a + bb - 2.0)));
        const float k3 = (float)((n + a - 1.0) * (n + bb - 1.0) * (2.0 * n + a + bb) /
                                 (n * (n + a + bb) * (2.0 * n + a + bb - 2.0)));
        const float pn0 = (k1 * t0 + k2) * p0 - k3 * pm0;
        const float pn1 = (k1 * t1 + k2) * p1 - k3 * pm1;
        pm0 = p0; pm1 = p1;
        p0 = pn0; p1 = pn1;
        stp(n, p0, p1);
    }
}

// ---------------------------------------------------------------------------
// Kernel 3: HMMA GEMM. C[b][o] = bias[o] + J[b]·(Wh+Wl)[o]  (2 products)
// 128x128x64 CTA tile, 3-stage cp.async, 8 warps (4x2 grid of 32x64 tiles),
// mma.sync m16n8k16 fp16 -> fp32 register accumulators.
// smem stage s at base + s*49152: {A=J (16KB), Wh (16KB), Wl (16KB)}, SWZ rows
// ---------------------------------------------------------------------------
#define SLOT_BYTES 49152
#define SMEM_TOTAL (STAGES * SLOT_BYTES + 1024)

__global__ void __launch_bounds__(256, 1) gemm_hmma(float* __restrict__ C) {
    extern __shared__ __align__(1024) char smem_raw[];
    const uint32_t sbr = s2u(smem_raw);
    const uint32_t ab = (sbr + 1023u) & ~1023u;   // 1024-aligned smem base

    const int tid  = threadIdx.x;
    const int wid  = tid >> 5;
    const int lane = tid & 31;
    const int bm = blockIdx.y * BM;
    const int bn = blockIdx.x * BN;

    const int wm = (wid >> 1) * 32;   // warp M offset (4 warps along M)
    const int wn = (wid & 1) * 64;    // warp N offset (2 warps along N)

    // ---- cp.async mapping: 3 tiles x 1024 16B-chunks / 256 threads
    uint32_t dsw[4];
    size_t aoff[4], boff[4];
#pragma unroll
    for (int j = 0; j < 4; j++) {
        const int c = tid + 256 * j;
        const int row = c >> 3;
        const int col = c & 7;
        dsw[j] = SWZ((uint32_t)(row * 128 + col * 16));
        aoff[j] = (size_t)(bm + row) * KK + col * 8;
        boff[j] = (size_t)(bn + row) * KK + col * 8;
    }

    auto load_tile = [&](int kt, int s) {
        const uint32_t base = ab + (uint32_t)s * SLOT_BYTES;
        const size_t ko = (size_t)kt * BK;
#pragma unroll
        for (int j = 0; j < 4; j++) {
            CP16(base +          dsw[j], g_J  + aoff[j] + ko);
            CP16(base + 16384u + dsw[j], g_Wh + boff[j] + ko);
            CP16(base + 32768u + dsw[j], g_Wl + boff[j] + ko);
        }
        asm volatile("cp.async.commit_group;" ::: "memory");
    };

    // ---- ldmatrix per-lane address pre-terms
    uint32_t aTerm[2], aRk[2];
    const uint32_t ahi = (uint32_t)(lane >> 4);
#pragma unroll
    for (int mb = 0; mb < 2; mb++) {
        const uint32_t ra = (uint32_t)(wm + mb * 16 + (lane & 15));
        aTerm[mb] = ra * 128u;
        aRk[mb]   = ra & 7u;
    }
    uint32_t bTerm[4], bRk[4];
    const uint32_t bhi = (uint32_t)((lane >> 3) & 1);
#pragma unroll
    for (int p = 0; p < 4; p++) {
        const uint32_t rb = (uint32_t)(wn + p * 16 + ((lane >> 4) << 3) + (lane & 7));
        bTerm[p] = rb * 128u;
        bRk[p]   = rb & 7u;
    }

    float acc[2][8][4];
#pragma unroll
    for (int mb = 0; mb < 2; mb++)
#pragma unroll
        for (int nb = 0; nb < 8; nb++)
#pragma unroll
            for (int q = 0; q < 4; q++) acc[mb][nb][q] = 0.f;

    // prologue: stages 0,1
    load_tile(0, 0);
    load_tile(1, 1);

#pragma unroll 1
    for (int kt = 0; kt < NTILE; kt++) {
        if (kt < NTILE - 1) asm volatile("cp.async.wait_group 1;" ::: "memory");
        else                asm volatile("cp.async.wait_group 0;" ::: "memory");
        __syncthreads();

        if (kt + 2 < NTILE) load_tile(kt + 2, (kt + 2) % STAGES);

        const uint32_t sb = ab + (uint32_t)(kt % STAGES) * SLOT_BYTES;

#pragma unroll
        for (int ks = 0; ks < 4; ks++) {
            const uint32_t kcA = 2u * ks + ahi;
            const uint32_t kcB = 2u * ks + bhi;

            uint32_t av[2][4];
#pragma unroll
            for (int mb = 0; mb < 2; mb++) {
                const uint32_t off = aTerm[mb] + ((kcA ^ aRk[mb]) << 4);
                LDSM4(av[mb][0], av[mb][1], av[mb][2], av[mb][3], sb + off);
            }

#pragma unroll
            for (int p = 0; p < 4; p++) {
                const uint32_t off = bTerm[p] + ((kcB ^ bRk[p]) << 4);
                uint32_t bh[4], bl[4];
                LDSM4(bh[0], bh[1], bh[2], bh[3], sb + 16384u + off);
                LDSM4(bl[0], bl[1], bl[2], bl[3], sb + 32768u + off);
                const int n0 = 2 * p, n1 = 2 * p + 1;
                // J · Wh
                MMA(acc[0][n0], av[0], bh[0], bh[1]);
                MMA(acc[0][n1], av[0], bh[2], bh[3]);
                MMA(acc[1][n0], av[1], bh[0], bh[1]);
                MMA(acc[1][n1], av[1], bh[2], bh[3]);
                // J · Wl
                MMA(acc[0][n0], av[0], bl[0], bl[1]);
                MMA(acc[0][n1], av[0], bl[2], bl[3]);
                MMA(acc[1][n0], av[1], bl[0], bl[1]);
                MMA(acc[1][n1], av[1], bl[2], bl[3]);
            }
        }
    }

    // epilogue: fragment -> global, + bias
#pragma unroll
    for (int mb = 0; mb < 2; mb++) {
        const int row0 = bm + wm + mb * 16 + (lane >> 2);
#pragma unroll
        for (int nb = 0; nb < 8; nb++) {
            const int cn = bn + wn + nb * 8 + (lane & 3) * 2;
            const float b0 = g_bias[cn];
            const float b1 = g_bias[cn + 1];
            float2 v0 = make_float2(acc[mb][nb][0] + b0, acc[mb][nb][1] + b1);
            float2 v1 = make_float2(acc[mb][nb][2] + b0, acc[mb][nb][3] + b1);
            *(float2*)(C + (size_t)row0 * OUT_SZ + cn)       = v0;
            *(float2*)(C + (size_t)(row0 + 8) * OUT_SZ + cn) = v1;
        }
    }
}

// ---------------------------------------------------------------------------
extern "C" void kernel_launch(void* const* d_in, const int* in_sizes, int n_in,
                              void* d_out, int out_size) {
    const float* x       = (const float*)d_in[0];  // [4096, 512]
    const float* weights = (const float*)d_in[1];  // [512, 512]
    const float* coeff   = (const float*)d_in[2];  // [512, 512, 9]
    float* out = (float*)d_out;                    // [4096, 512]

    cudaFuncSetAttribute(gemm_hmma, cudaFuncAttributeMaxDynamicSharedMemorySize,
                         SMEM_TOTAL);

    wprep_kernel<<<OUT_SZ, 256>>>(weights, coeff);
    jgen_kernel<<<(BATCH * IN_SZ / 2) / 256, 256>>>(x);
    dim3 grid(OUT_SZ / BN, BATCH / BM);
    gemm_hmma<<<grid, 256, SMEM_TOTAL>>>(out);
}

// round 13
// speedup vs baseline: 7.1178x; 1.6297x over previous
#include <cuda_runtime.h>
#include <cuda_fp16.h>
#include <cstdint>
#include <math.h>

#define ORDER   8
#define IN_SZ   512
#define OUT_SZ  512
#define BATCH   4096
#define KK      4096              // inner dim (k=1..8 folded; k=0 -> bias)
#define BM      128
#define BN      128
#define BK      64
#define NTILE   (KK / BK)         // 64 k-chunks
#define STAGES  4

// single fp16 operands: J rounding + W rounding each ~2^-12 rms, independent
__device__ __align__(256) __half g_J[(size_t)BATCH  * KK];
__device__ __align__(256) __half g_W[(size_t)OUT_SZ * KK];
__device__ float g_bias[OUT_SZ];

// ---------------------------------------------------------------------------
// helpers (baseline PTX only: cp.async / ldmatrix / mma.sync — no tcgen05)
// ---------------------------------------------------------------------------
__device__ __forceinline__ uint32_t s2u(const void* p) {
    uint32_t a;
    asm("{ .reg .u64 t; cvta.to.shared.u64 t, %1; cvt.u32.u64 %0, t; }"
        : "=r"(a) : "l"(p));
    return a;
}

#define SWZ(x) ((x) ^ (((x) >> 3) & 0x70))   // 128B-row xor swizzle

#define CP16(dst, src) \
    asm volatile("cp.async.cg.shared.global [%0], [%1], 16;" \
                 :: "r"(dst), "l"(__cvta_generic_to_global(src)) : "memory")

#define LDSM4(r0, r1, r2, r3, addr) \
    asm volatile("ldmatrix.sync.aligned.m8n8.x4.shared.b16 {%0,%1,%2,%3}, [%4];" \
                 : "=r"(r0), "=r"(r1), "=r"(r2), "=r"(r3) : "r"(addr))

#define MMA(c, a, b0, b1) \
    asm volatile("mma.sync.aligned.m16n8k16.row.col.f32.f16.f16.f32 " \
                 "{%0,%1,%2,%3},{%4,%5,%6,%7},{%8,%9},{%0,%1,%2,%3};" \
                 : "+f"((c)[0]), "+f"((c)[1]), "+f"((c)[2]), "+f"((c)[3]) \
                 : "r"((a)[0]), "r"((a)[1]), "r"((a)[2]), "r"((a)[3]), \
                   "r"(b0), "r"(b1))

// ---------------------------------------------------------------------------
// Kernel 1: W[o][cc] = fp16(coeff[o][i][k]*w[o][i]); bias from k=0 (J_0==1)
// ---------------------------------------------------------------------------
__global__ void wprep_kernel(const float* __restrict__ w,
                             const float* __restrict__ coeff) {
    const int o = blockIdx.x;
    __shared__ float red[256];
    float acc = 0.f;
    for (int i = threadIdx.x; i < IN_SZ; i += 256) {
        const float wv = w[o * IN_SZ + i];
        const float* c = coeff + ((size_t)o * IN_SZ + i) * (ORDER + 1);
        acc += c[0] * wv;
#pragma unroll
        for (int k = 1; k <= ORDER; k++)
            g_W[(size_t)o * KK + (size_t)(k - 1) * IN_SZ + i] =
                __float2half_rn(c[k] * wv);
    }
    red[threadIdx.x] = acc;
    __syncthreads();
    for (int s = 128; s > 0; s >>= 1) {
        if (threadIdx.x < s) red[threadIdx.x] += red[threadIdx.x + s];
        __syncthreads();
    }
    if (threadIdx.x == 0) g_bias[o] = red[0];
}

// ---------------------------------------------------------------------------
// Kernel 2: Jacobi values (alpha=beta=1) -> fp16, 2 elems/thread
// ---------------------------------------------------------------------------
__global__ void jgen_kernel(const float* __restrict__ x) {
    const int g = blockIdx.x * blockDim.x + threadIdx.x;
    const int e = g * 2;
    const int b = e >> 9;
    const int i = e & (IN_SZ - 1);
    const float2 xv = *(const float2*)(x + e);
    const float t0 = tanhf(xv.x);
    const float t1 = tanhf(xv.y);

    const size_t base = (size_t)b * KK + i;

    float pm0 = 1.0f, pm1 = 1.0f;
    float p0 = 2.0f * t0, p1 = 2.0f * t1;

    auto stp = [&](int n, float a0, float a1) {
        *(__half2*)(g_J + base + (size_t)(n - 1) * IN_SZ) =
            __halves2half2(__float2half_rn(a0), __float2half_rn(a1));
    };

    stp(1, p0, p1);
#pragma unroll
    for (int n = 2; n <= ORDER; n++) {
        const double a = 1.0, bb = 1.0;
        const float k1 = (float)((2.0 * n + a + bb) * (2.0 * n + a + bb - 1.0) /
                                 (2.0 * n * (n + a + bb)));
        const float k2 = (float)((2.0 * n + a + bb - 1.0) * (a * a - bb * bb) /
                                 (2.0 * n * (n + a + bb) * (2.0 * n + a + bb - 2.0)));
        const float k3 = (float)((n + a - 1.0) * (n + bb - 1.0) * (2.0 * n + a + bb) /
                                 (n * (n + a + bb) * (2.0 * n + a + bb - 2.0)));
        const float pn0 = (k1 * t0 + k2) * p0 - k3 * pm0;
        const float pn1 = (k1 * t1 + k2) * p1 - k3 * pm1;
        pm0 = p0; pm1 = p1;
        p0 = pn0; p1 = pn1;
        stp(n, p0, p1);
    }
}

// ---------------------------------------------------------------------------
// Kernel 3: HMMA GEMM. C[b][o] = bias[o] + J[b]·W[o]  (single fp16 product)
// 128x128x64 CTA tile, 4-stage cp.async, 8 warps (4x2 grid of 32x64 tiles),
// mma.sync m16n8k16 fp16 -> fp32 register accumulators.
// smem stage s at base + s*32768: {A=J (16KB), W (16KB)}, SWZ rows of 128B
// ---------------------------------------------------------------------------
#define SLOT_BYTES 32768
#define SMEM_TOTAL (STAGES * SLOT_BYTES + 1024)

__global__ void __launch_bounds__(256, 1) gemm_hmma(float* __restrict__ C) {
    extern __shared__ __align__(1024) char smem_raw[];
    const uint32_t sbr = s2u(smem_raw);
    const uint32_t ab = (sbr + 1023u) & ~1023u;   // 1024-aligned smem base

    const int tid  = threadIdx.x;
    const int wid  = tid >> 5;
    const int lane = tid & 31;
    const int bm = blockIdx.y * BM;
    const int bn = blockIdx.x * BN;

    const int wm = (wid >> 1) * 32;   // warp M offset (4 warps along M)
    const int wn = (wid & 1) * 64;    // warp N offset (2 warps along N)

    // ---- cp.async mapping: 2 tiles x 1024 16B-chunks / 256 threads
    uint32_t dsw[4];
    size_t aoff[4], boff[4];
#pragma unroll
    for (int j = 0; j < 4; j++) {
        const int c = tid + 256 * j;
        const int row = c >> 3;
        const int col = c & 7;
        dsw[j] = SWZ((uint32_t)(row * 128 + col * 16));
        aoff[j] = (size_t)(bm + row) * KK + col * 8;
        boff[j] = (size_t)(bn + row) * KK + col * 8;
    }

    auto load_tile = [&](int kt, int s) {
        const uint32_t base = ab + (uint32_t)s * SLOT_BYTES;
        const size_t ko = (size_t)kt * BK;
#pragma unroll
        for (int j = 0; j < 4; j++) {
            CP16(base +          dsw[j], g_J + aoff[j] + ko);
            CP16(base + 16384u + dsw[j], g_W + boff[j] + ko);
        }
        asm volatile("cp.async.commit_group;" ::: "memory");
    };

    // ---- ldmatrix per-lane address pre-terms
    uint32_t aTerm[2], aRk[2];
    const uint32_t ahi = (uint32_t)(lane >> 4);
#pragma unroll
    for (int mb = 0; mb < 2; mb++) {
        const uint32_t ra = (uint32_t)(wm + mb * 16 + (lane & 15));
        aTerm[mb] = ra * 128u;
        aRk[mb]   = ra & 7u;
    }
    uint32_t bTerm[4], bRk[4];
    const uint32_t bhi = (uint32_t)((lane >> 3) & 1);
#pragma unroll
    for (int p = 0; p < 4; p++) {
        const uint32_t rb = (uint32_t)(wn + p * 16 + ((lane >> 4) << 3) + (lane & 7));
        bTerm[p] = rb * 128u;
        bRk[p]   = rb & 7u;
    }

    float acc[2][8][4];
#pragma unroll
    for (int mb = 0; mb < 2; mb++)
#pragma unroll
        for (int nb = 0; nb < 8; nb++)
#pragma unroll
            for (int q = 0; q < 4; q++) acc[mb][nb][q] = 0.f;

    // prologue: stages 0..2 (keep 1 slot free)
    load_tile(0, 0);
    load_tile(1, 1);
    load_tile(2, 2);

#pragma unroll 1
    for (int kt = 0; kt < NTILE; kt++) {
        if (kt < NTILE - 2)       asm volatile("cp.async.wait_group 2;" ::: "memory");
        else if (kt == NTILE - 2) asm volatile("cp.async.wait_group 1;" ::: "memory");
        else                      asm volatile("cp.async.wait_group 0;" ::: "memory");
        __syncthreads();

        if (kt + 3 < NTILE) load_tile(kt + 3, (kt + 3) % STAGES);

        const uint32_t sb = ab + (uint32_t)(kt % STAGES) * SLOT_BYTES;

#pragma unroll
        for (int ks = 0; ks < 4; ks++) {
            const uint32_t kcA = 2u * ks + ahi;
            const uint32_t kcB = 2u * ks + bhi;

            uint32_t av[2][4];
#pragma unroll
            for (int mb = 0; mb < 2; mb++) {
                const uint32_t off = aTerm[mb] + ((kcA ^ aRk[mb]) << 4);
                LDSM4(av[mb][0], av[mb][1], av[mb][2], av[mb][3], sb + off);
            }

#pragma unroll
            for (int p = 0; p < 4; p++) {
                const uint32_t off = bTerm[p] + ((kcB ^ bRk[p]) << 4);
                uint32_t bv[4];
                LDSM4(bv[0], bv[1], bv[2], bv[3], sb + 16384u + off);
                const int n0 = 2 * p, n1 = 2 * p + 1;
                MMA(acc[0][n0], av[0], bv[0], bv[1]);
                MMA(acc[0][n1], av[0], bv[2], bv[3]);
                MMA(acc[1][n0], av[1], bv[0], bv[1]);
                MMA(acc[1][n1], av[1], bv[2], bv[3]);
            }
        }
    }

    // epilogue: fragment -> global, + bias
#pragma unroll
    for (int mb = 0; mb < 2; mb++) {
        const int row0 = bm + wm + mb * 16 + (lane >> 2);
#pragma unroll
        for (int nb = 0; nb < 8; nb++) {
            const int cn = bn + wn + nb * 8 + (lane & 3) * 2;
            const float b0 = g_bias[cn];
            const float b1 = g_bias[cn + 1];
            float2 v0 = make_float2(acc[mb][nb][0] + b0, acc[mb][nb][1] + b1);
            float2 v1 = make_float2(acc[mb][nb][2] + b0, acc[mb][nb][3] + b1);
            *(float2*)(C + (size_t)row0 * OUT_SZ + cn)       = v0;
            *(float2*)(C + (size_t)(row0 + 8) * OUT_SZ + cn) = v1;
        }
    }
}

// ---------------------------------------------------------------------------
extern "C" void kernel_launch(void* const* d_in, const int* in_sizes, int n_in,
                              void* d_out, int out_size) {
    const float* x       = (const float*)d_in[0];  // [4096, 512]
    const float* weights = (const float*)d_in[1];  // [512, 512]
    const float* coeff   = (const float*)d_in[2];  // [512, 512, 9]
    float* out = (float*)d_out;                    // [4096, 512]

    cudaFuncSetAttribute(gemm_hmma, cudaFuncAttributeMaxDynamicSharedMemorySize,
                         SMEM_TOTAL);

    wprep_kernel<<<OUT_SZ, 256>>>(weights, coeff);
    jgen_kernel<<<(BATCH * IN_SZ / 2) / 256, 256>>>(x);
    dim3 grid(OUT_SZ / BN, BATCH / BM);
    gemm_hmma<<<grid, 256, SMEM_TOTAL>>>(out);
}